// round 8
// baseline (speedup 1.0000x reference)
#include <cuda_runtime.h>
#include <cuda_bf16.h>
#include <cstdint>

// Problem constants (fixed by the reference)
#define N_NODES 50000
#define N_EDGES 800000
#define IN_CH   128
#define OUT_CH  64
#define SELF_LOOP_W 2.0f

// Scratch (device globals: no allocation allowed)
__device__ float  g_deg[N_NODES];
__device__ float  g_dinv[N_NODES];
__device__ int    g_cnt[N_NODES];
__device__ int    g_off[N_NODES + 1];
__device__ int    g_cur[N_NODES];
__device__ float2 g_edges[N_EDGES];       // (src bits, normalized weight), CSR by target
__device__ float  g_xw[N_NODES * OUT_CH];
__device__ int    g_is64;                 // 1 if edge_index is int64, 0 if int32

// ---------------------------------------------------------------------------
// 0) Detect edge_index dtype (int64 => odd 32-bit words are all-zero high halves).
__global__ void detect_dtype_kernel(const unsigned* __restrict__ p32) {
    __shared__ unsigned red[256];
    unsigned acc = 0;
#pragma unroll
    for (int j = 0; j < 4; j++) {
        int k = threadIdx.x * 4 + j;            // 0..1023
        int pos = 2 * (k * 390 + 1) + 1;        // odd positions, max 797943 < 800000
        acc |= p32[pos];
    }
    red[threadIdx.x] = acc;
    __syncthreads();
    for (int s = 128; s > 0; s >>= 1) {
        if (threadIdx.x < s) red[threadIdx.x] |= red[threadIdx.x + s];
        __syncthreads();
    }
    if (threadIdx.x == 0) g_is64 = (red[0] == 0) ? 1 : 0;
}

__device__ __forceinline__ int edge_src(const int* __restrict__ p32, int e, int is64) {
    int v = is64 ? p32[2 * e] : p32[e];
    return (unsigned)v < N_NODES ? v : 0;
}
__device__ __forceinline__ int edge_dst(const int* __restrict__ p32, int e, int is64) {
    int v = is64 ? p32[2 * (N_EDGES + e)] : p32[N_EDGES + e];
    return (unsigned)v < N_NODES ? v : 0;
}

// ---------------------------------------------------------------------------
// 1) init: deg = 2.0 (self loop), cnt = 0
__global__ void init_kernel() {
    int i = blockIdx.x * blockDim.x + threadIdx.x;
    if (i < N_NODES) { g_deg[i] = SELF_LOOP_W; g_cnt[i] = 0; }
}

// 2) histogram + degree: cnt[t]++, deg[t] += ew
__global__ void hist_kernel(const int* __restrict__ ei,
                            const float* __restrict__ ew) {
    int e = blockIdx.x * blockDim.x + threadIdx.x;
    if (e >= N_EDGES) return;
    int is64 = g_is64;
    int t = edge_dst(ei, e, is64);
    atomicAdd(&g_cnt[t], 1);
    atomicAdd(&g_deg[t], ew[e]);
}

// 3) single-block pass: exclusive scan of g_cnt -> g_off/g_cur, g_off[N]=E,
//    and dinv = rsqrt(deg) fused in (deg is final after hist).
#define SCAN_T 1024
__global__ __launch_bounds__(SCAN_T) void scan_dinv_kernel() {
    __shared__ int part[SCAN_T];
    const int CHUNK = (N_NODES + SCAN_T - 1) / SCAN_T;   // 49
    int t  = threadIdx.x;
    int lo = t * CHUNK;
    int hi = lo + CHUNK; if (hi > N_NODES) hi = N_NODES;
    if (lo > N_NODES) lo = N_NODES;

    int sum = 0;
    for (int i = lo; i < hi; i++) {
        sum += g_cnt[i];
        float d = g_deg[i];
        g_dinv[i] = d > 0.0f ? rsqrtf(d) : 0.0f;
    }
    part[t] = sum;
    __syncthreads();
    // Hillis-Steele inclusive scan over per-thread sums
    for (int off = 1; off < SCAN_T; off <<= 1) {
        int v = part[t];
        int add = (t >= off) ? part[t - off] : 0;
        __syncthreads();
        part[t] = v + add;
        __syncthreads();
    }
    int base = (t == 0) ? 0 : part[t - 1];   // exclusive base for this chunk
    for (int i = lo; i < hi; i++) {
        int c = g_cnt[i];
        g_off[i] = base;
        g_cur[i] = base;
        base += c;
    }
    if (t == SCAN_T - 1) g_off[N_NODES] = part[SCAN_T - 1];
}

// 4) reorder edges into CSR-by-target, folding in the normalization weight
__global__ void reorder_kernel(const int* __restrict__ ei,
                               const float* __restrict__ ew) {
    int e = blockIdx.x * blockDim.x + threadIdx.x;
    if (e >= N_EDGES) return;
    int is64 = g_is64;
    int s = edge_src(ei, e, is64);
    int t = edge_dst(ei, e, is64);
    float w = g_dinv[s] * ew[e] * g_dinv[t];
    int pos = atomicAdd(&g_cur[t], 1);
    g_edges[pos] = make_float2(__int_as_float(s), w);
}

// ---------------------------------------------------------------------------
// 5) GEMM: xw[N,64] = x[N,128] @ W[128,64], fp32, smem-tiled.
#define GEMM_ROWS 64
#define XS_STRIDE 132
__global__ __launch_bounds__(256) void gemm_kernel(const float* __restrict__ x,
                                                   const float* __restrict__ W) {
    __shared__ float Ws[IN_CH * OUT_CH];        // 32KB
    __shared__ float Xs[GEMM_ROWS * XS_STRIDE]; // ~33KB
    int node0 = blockIdx.x * GEMM_ROWS;

    for (int i = threadIdx.x; i < IN_CH * OUT_CH / 4; i += 256)
        ((float4*)Ws)[i] = ((const float4*)W)[i];

    for (int i = threadIdx.x; i < GEMM_ROWS * (IN_CH / 4); i += 256) {
        int r = i / (IN_CH / 4);
        int c = i % (IN_CH / 4);
        int node = node0 + r;
        float4 v = make_float4(0.f, 0.f, 0.f, 0.f);
        if (node < N_NODES)
            v = ((const float4*)(x + (size_t)node * IN_CH))[c];
        float* dst = &Xs[r * XS_STRIDE + c * 4];
        dst[0] = v.x; dst[1] = v.y; dst[2] = v.z; dst[3] = v.w;
    }
    __syncthreads();

    int r    = threadIdx.x >> 2;
    int cg   = threadIdx.x & 3;
    int node = node0 + r;

    float acc[16];
#pragma unroll
    for (int j = 0; j < 16; j++) acc[j] = 0.0f;

#pragma unroll 4
    for (int k = 0; k < IN_CH; k++) {
        float xv = Xs[r * XS_STRIDE + k];
#pragma unroll
        for (int j = 0; j < 16; j++)
            acc[j] += xv * Ws[k * OUT_CH + cg + 4 * j];
    }

    if (node < N_NODES) {
        float* o = g_xw + (size_t)node * OUT_CH;
#pragma unroll
        for (int j = 0; j < 16; j++)
            o[cg + 4 * j] = acc[j];
    }
}

// ---------------------------------------------------------------------------
// 6) gather: out[n] = (2*dinv[n]^2)*xw[n] + b + sum_{e->n} w_e * xw[src_e]
//    16 threads per node, one float4 accumulator each. No atomics.
__global__ __launch_bounds__(256) void gather_kernel(const float* __restrict__ b,
                                                     float* __restrict__ out) {
    int node = blockIdx.x * 16 + (threadIdx.x >> 4);
    int lane = threadIdx.x & 15;
    if (node >= N_NODES) return;

    const float4* xw4 = (const float4*)g_xw;

    float d  = g_dinv[node];
    float sw = SELF_LOOP_W * d * d;
    float4 v  = xw4[node * 16 + lane];
    float4 bb = ((const float4*)b)[lane];
    float4 acc = make_float4(fmaf(v.x, sw, bb.x), fmaf(v.y, sw, bb.y),
                             fmaf(v.z, sw, bb.z), fmaf(v.w, sw, bb.w));

    int beg = g_off[node];
    int end = g_off[node + 1];
#pragma unroll 4
    for (int j = beg; j < end; j++) {
        float2 m = g_edges[j];
        int   s = __float_as_int(m.x);
        float w = m.y;
        float4 u = xw4[s * 16 + lane];
        acc.x = fmaf(u.x, w, acc.x);
        acc.y = fmaf(u.y, w, acc.y);
        acc.z = fmaf(u.z, w, acc.z);
        acc.w = fmaf(u.w, w, acc.w);
    }
    ((float4*)out)[node * 16 + lane] = acc;
}

// ---------------------------------------------------------------------------
extern "C" void kernel_launch(void* const* d_in, const int* in_sizes, int n_in,
                              void* d_out, int out_size) {
    const float* x  = (const float*)d_in[0];   // [N, 128]
    const int*   ei = (const int*)d_in[1];     // [2, E] int32 or int64 (detected)
    const float* ew = (const float*)d_in[2];   // [E]
    const float* W  = (const float*)d_in[3];   // [128, 64]
    const float* b  = (const float*)d_in[4];   // [64]
    float* out = (float*)d_out;                // [N, 64]
    (void)in_sizes; (void)n_in; (void)out_size;

    detect_dtype_kernel<<<1, 256>>>((const unsigned*)d_in[1]);
    init_kernel<<<(N_NODES + 255) / 256, 256>>>();
    hist_kernel<<<(N_EDGES + 255) / 256, 256>>>(ei, ew);
    scan_dinv_kernel<<<1, SCAN_T>>>();
    reorder_kernel<<<(N_EDGES + 255) / 256, 256>>>(ei, ew);
    gemm_kernel<<<(N_NODES + GEMM_ROWS - 1) / GEMM_ROWS, 256>>>(x, W);
    gather_kernel<<<(N_NODES + 15) / 16, 256>>>(b, out);
}

// round 10
// speedup vs baseline: 2.0236x; 2.0236x over previous
#include <cuda_runtime.h>
#include <cuda_bf16.h>
#include <cstdint>

// Problem constants (fixed by the reference)
#define N_NODES 50000
#define N_EDGES 800000
#define IN_CH   128
#define OUT_CH  64
#define SELF_LOOP_W 2.0f

#define SB 512                               // scan block size
#define NB ((N_NODES + SB - 1) / SB)         // 98 scan blocks

// Scratch (device globals: no allocation allowed)
__device__ float  g_deg[N_NODES];
__device__ float  g_dinv[N_NODES];
__device__ int    g_cnt[N_NODES];
__device__ int    g_off[N_NODES + 1];
__device__ int    g_cur[N_NODES];
__device__ int    g_bsum[NB];
__device__ int    g_bbase[NB];
__device__ float2 g_edges[N_EDGES];          // (src bits, normalized weight), CSR by target
__device__ float  g_xw[N_NODES * OUT_CH];
__device__ int    g_is64;                    // 1 if edge_index is int64, 0 if int32

// ---------------------------------------------------------------------------
// 0) Detect edge_index dtype (int64 => odd 32-bit words are all-zero high halves).
__global__ void detect_dtype_kernel(const unsigned* __restrict__ p32) {
    __shared__ unsigned red[256];
    unsigned acc = 0;
#pragma unroll
    for (int j = 0; j < 4; j++) {
        int k = threadIdx.x * 4 + j;            // 0..1023
        int pos = 2 * (k * 390 + 1) + 1;        // odd positions, max 797943 < 800000
        acc |= p32[pos];
    }
    red[threadIdx.x] = acc;
    __syncthreads();
    for (int s = 128; s > 0; s >>= 1) {
        if (threadIdx.x < s) red[threadIdx.x] |= red[threadIdx.x + s];
        __syncthreads();
    }
    if (threadIdx.x == 0) g_is64 = (red[0] == 0) ? 1 : 0;
}

__device__ __forceinline__ int edge_src(const int* __restrict__ p32, int e, int is64) {
    int v = is64 ? p32[2 * e] : p32[e];
    return (unsigned)v < N_NODES ? v : 0;
}
__device__ __forceinline__ int edge_dst(const int* __restrict__ p32, int e, int is64) {
    int v = is64 ? p32[2 * (N_EDGES + e)] : p32[N_EDGES + e];
    return (unsigned)v < N_NODES ? v : 0;
}

// ---------------------------------------------------------------------------
// 1) init: deg = 2.0 (self loop), cnt = 0
__global__ void init_kernel() {
    int i = blockIdx.x * blockDim.x + threadIdx.x;
    if (i < N_NODES) { g_deg[i] = SELF_LOOP_W; g_cnt[i] = 0; }
}

// 2) histogram + degree: cnt[t]++, deg[t] += ew
__global__ void hist_kernel(const int* __restrict__ ei,
                            const float* __restrict__ ew) {
    int e = blockIdx.x * blockDim.x + threadIdx.x;
    if (e >= N_EDGES) return;
    int is64 = g_is64;
    int t = edge_dst(ei, e, is64);
    atomicAdd(&g_cnt[t], 1);
    atomicAdd(&g_deg[t], ew[e]);
}

// ---------------------------------------------------------------------------
// 3a) scan pass A: per-block sums of g_cnt + dinv (fully parallel).
__global__ __launch_bounds__(SB) void scanA_kernel() {
    __shared__ int red[SB];
    int i = blockIdx.x * SB + threadIdx.x;
    int c = 0;
    if (i < N_NODES) {
        c = g_cnt[i];
        float d = g_deg[i];
        g_dinv[i] = d > 0.0f ? rsqrtf(d) : 0.0f;
    }
    red[threadIdx.x] = c;
    __syncthreads();
    for (int s = SB / 2; s > 0; s >>= 1) {
        if (threadIdx.x < s) red[threadIdx.x] += red[threadIdx.x + s];
        __syncthreads();
    }
    if (threadIdx.x == 0) g_bsum[blockIdx.x] = red[0];
}

// 3b) scan pass B: exclusive scan of the 98 block sums (one tiny block).
__global__ __launch_bounds__(128) void scanB_kernel() {
    __shared__ int part[128];
    int t = threadIdx.x;
    int v = (t < NB) ? g_bsum[t] : 0;
    part[t] = v;
    __syncthreads();
    for (int off = 1; off < 128; off <<= 1) {
        int a = part[t];
        int add = (t >= off) ? part[t - off] : 0;
        __syncthreads();
        part[t] = a + add;
        __syncthreads();
    }
    if (t < NB) g_bbase[t] = part[t] - v;           // exclusive
    if (t == 127) g_off[N_NODES] = part[127];       // total = E
}

// 3c) scan pass C: per-block exclusive scan of counts + block base -> g_off/g_cur.
__global__ __launch_bounds__(SB) void scanC_kernel() {
    __shared__ int part[SB];
    int i = blockIdx.x * SB + threadIdx.x;
    int c = (i < N_NODES) ? g_cnt[i] : 0;
    part[threadIdx.x] = c;
    __syncthreads();
    for (int off = 1; off < SB; off <<= 1) {
        int a = part[threadIdx.x];
        int add = (threadIdx.x >= off) ? part[threadIdx.x - off] : 0;
        __syncthreads();
        part[threadIdx.x] = a + add;
        __syncthreads();
    }
    if (i < N_NODES) {
        int excl = part[threadIdx.x] - c + g_bbase[blockIdx.x];
        g_off[i] = excl;
        g_cur[i] = excl;
    }
}

// ---------------------------------------------------------------------------
// 4) reorder edges into CSR-by-target, folding in the normalization weight
__global__ void reorder_kernel(const int* __restrict__ ei,
                               const float* __restrict__ ew) {
    int e = blockIdx.x * blockDim.x + threadIdx.x;
    if (e >= N_EDGES) return;
    int is64 = g_is64;
    int s = edge_src(ei, e, is64);
    int t = edge_dst(ei, e, is64);
    float w = g_dinv[s] * ew[e] * g_dinv[t];
    int pos = atomicAdd(&g_cur[t], 1);
    g_edges[pos] = make_float2(__int_as_float(s), w);
}

// ---------------------------------------------------------------------------
// 5) GEMM: xw[N,64] = x[N,128] @ W[128,64], fp32, smem-tiled.
#define GEMM_ROWS 64
#define XS_STRIDE 132
__global__ __launch_bounds__(256) void gemm_kernel(const float* __restrict__ x,
                                                   const float* __restrict__ W) {
    __shared__ float Ws[IN_CH * OUT_CH];        // 32KB
    __shared__ float Xs[GEMM_ROWS * XS_STRIDE]; // ~33KB
    int node0 = blockIdx.x * GEMM_ROWS;

    for (int i = threadIdx.x; i < IN_CH * OUT_CH / 4; i += 256)
        ((float4*)Ws)[i] = ((const float4*)W)[i];

    for (int i = threadIdx.x; i < GEMM_ROWS * (IN_CH / 4); i += 256) {
        int r = i / (IN_CH / 4);
        int c = i % (IN_CH / 4);
        int node = node0 + r;
        float4 v = make_float4(0.f, 0.f, 0.f, 0.f);
        if (node < N_NODES)
            v = ((const float4*)(x + (size_t)node * IN_CH))[c];
        float* dst = &Xs[r * XS_STRIDE + c * 4];
        dst[0] = v.x; dst[1] = v.y; dst[2] = v.z; dst[3] = v.w;
    }
    __syncthreads();

    int r    = threadIdx.x >> 2;
    int cg   = threadIdx.x & 3;
    int node = node0 + r;

    float acc[16];
#pragma unroll
    for (int j = 0; j < 16; j++) acc[j] = 0.0f;

#pragma unroll 4
    for (int k = 0; k < IN_CH; k++) {
        float xv = Xs[r * XS_STRIDE + k];
#pragma unroll
        for (int j = 0; j < 16; j++)
            acc[j] += xv * Ws[k * OUT_CH + cg + 4 * j];
    }

    if (node < N_NODES) {
        float* o = g_xw + (size_t)node * OUT_CH;
#pragma unroll
        for (int j = 0; j < 16; j++)
            o[cg + 4 * j] = acc[j];
    }
}

// ---------------------------------------------------------------------------
// 6) gather: out[n] = (2*dinv[n]^2)*xw[n] + b + sum_{e->n} w_e * xw[src_e]
//    16 threads per node, one float4 accumulator each. No atomics.
__global__ __launch_bounds__(256) void gather_kernel(const float* __restrict__ b,
                                                     float* __restrict__ out) {
    int node = blockIdx.x * 16 + (threadIdx.x >> 4);
    int lane = threadIdx.x & 15;
    if (node >= N_NODES) return;

    const float4* xw4 = (const float4*)g_xw;

    float d  = g_dinv[node];
    float sw = SELF_LOOP_W * d * d;
    float4 v  = xw4[node * 16 + lane];
    float4 bb = ((const float4*)b)[lane];
    float4 acc = make_float4(fmaf(v.x, sw, bb.x), fmaf(v.y, sw, bb.y),
                             fmaf(v.z, sw, bb.z), fmaf(v.w, sw, bb.w));

    int beg = g_off[node];
    int end = g_off[node + 1];
#pragma unroll 4
    for (int j = beg; j < end; j++) {
        float2 m = g_edges[j];
        int   s = __float_as_int(m.x);
        float w = m.y;
        float4 u = xw4[s * 16 + lane];
        acc.x = fmaf(u.x, w, acc.x);
        acc.y = fmaf(u.y, w, acc.y);
        acc.z = fmaf(u.z, w, acc.z);
        acc.w = fmaf(u.w, w, acc.w);
    }
    ((float4*)out)[node * 16 + lane] = acc;
}

// ---------------------------------------------------------------------------
extern "C" void kernel_launch(void* const* d_in, const int* in_sizes, int n_in,
                              void* d_out, int out_size) {
    const float* x  = (const float*)d_in[0];   // [N, 128]
    const int*   ei = (const int*)d_in[1];     // [2, E] int32 or int64 (detected)
    const float* ew = (const float*)d_in[2];   // [E]
    const float* W  = (const float*)d_in[3];   // [128, 64]
    const float* b  = (const float*)d_in[4];   // [64]
    float* out = (float*)d_out;                // [N, 64]
    (void)in_sizes; (void)n_in; (void)out_size;

    detect_dtype_kernel<<<1, 256>>>((const unsigned*)d_in[1]);
    init_kernel<<<(N_NODES + 255) / 256, 256>>>();
    hist_kernel<<<(N_EDGES + 255) / 256, 256>>>(ei, ew);
    scanA_kernel<<<NB, SB>>>();
    scanB_kernel<<<1, 128>>>();
    scanC_kernel<<<NB, SB>>>();
    reorder_kernel<<<(N_EDGES + 255) / 256, 256>>>(ei, ew);
    gemm_kernel<<<(N_NODES + GEMM_ROWS - 1) / GEMM_ROWS, 256>>>(x, W);
    gather_kernel<<<(N_NODES + 15) / 16, 256>>>(b, out);
}

// round 13
// speedup vs baseline: 2.2234x; 1.0988x over previous
#include <cuda_runtime.h>
#include <cuda_fp16.h>
#include <cstdint>

// Problem constants (fixed by the reference)
#define N_NODES 50000
#define N_EDGES 800000
#define IN_CH   128
#define OUT_CH  64
#define SELF_LOOP_W 2.0f

#define SB 512                               // scan block size
#define NB ((N_NODES + SB - 1) / SB)         // 98 scan blocks

// Scratch (device globals: no allocation allowed)
__device__ unsigned long long g_cd[N_NODES]; // packed: count<<32 | fix24(sum ew)
__device__ float  g_dinv[N_NODES];
__device__ int    g_cnt[N_NODES];
__device__ int    g_off[N_NODES + 1];
__device__ int    g_cur[N_NODES];
__device__ int    g_bsum[NB];
__device__ int    g_bbase[NB];
__device__ float2 g_edges[N_EDGES];          // (src bits, normalized weight), CSR by target
__device__ __half g_xw[N_NODES * OUT_CH];    // fp16 transformed features (6.4MB)
__device__ int    g_is64;                    // 1 if edge_index is int64, 0 if int32

// ---------------------------------------------------------------------------
// 1) prep: zero packed counters everywhere; block 0 additionally sniffs the
//    edge_index dtype (int64 => odd 32-bit words are all-zero high halves).
__global__ void prep_kernel(const unsigned* __restrict__ p32) {
    int i = blockIdx.x * blockDim.x + threadIdx.x;
    if (i < N_NODES) g_cd[i] = 0ULL;

    if (blockIdx.x == 0) {
        __shared__ unsigned red[256];
        unsigned acc = 0;
#pragma unroll
        for (int j = 0; j < 4; j++) {
            int k = threadIdx.x * 4 + j;            // 0..1023
            int pos = 2 * (k * 390 + 1) + 1;        // odd positions, max 797943 < 800000
            acc |= p32[pos];
        }
        red[threadIdx.x] = acc;
        __syncthreads();
        for (int s = 128; s > 0; s >>= 1) {
            if (threadIdx.x < s) red[threadIdx.x] |= red[threadIdx.x + s];
            __syncthreads();
        }
        if (threadIdx.x == 0) g_is64 = (red[0] == 0) ? 1 : 0;
    }
}

__device__ __forceinline__ int edge_src(const int* __restrict__ p32, int e, int is64) {
    int v = is64 ? p32[2 * e] : p32[e];
    return (unsigned)v < N_NODES ? v : 0;
}
__device__ __forceinline__ int edge_dst(const int* __restrict__ p32, int e, int is64) {
    int v = is64 ? p32[2 * (N_EDGES + e)] : p32[N_EDGES + e];
    return (unsigned)v < N_NODES ? v : 0;
}

// ---------------------------------------------------------------------------
// 2) histogram + degree in ONE 64-bit atomic per edge:
//    high 32 bits: edge count; low 32 bits: sum of ew in 8.24 fixed point.
__global__ void hist_kernel(const int* __restrict__ ei,
                            const float* __restrict__ ew) {
    int e = blockIdx.x * blockDim.x + threadIdx.x;
    if (e >= N_EDGES) return;
    int is64 = g_is64;
    int t = edge_dst(ei, e, is64);
    unsigned fx = __float2uint_rn(ew[e] * 16777216.0f);   // ew in [0,1)
    atomicAdd(&g_cd[t], (1ULL << 32) | (unsigned long long)fx);
}

// ---------------------------------------------------------------------------
// 3a) scan pass A: unpack counts + compute dinv; per-block count sums.
__global__ __launch_bounds__(SB) void scanA_kernel() {
    __shared__ int red[SB];
    int i = blockIdx.x * SB + threadIdx.x;
    int c = 0;
    if (i < N_NODES) {
        unsigned long long cd = g_cd[i];
        c = (int)(cd >> 32);
        float deg = SELF_LOOP_W + (float)(unsigned)cd * (1.0f / 16777216.0f);
        g_dinv[i] = rsqrtf(deg);             // deg >= 2 always
        g_cnt[i]  = c;
    }
    red[threadIdx.x] = c;
    __syncthreads();
    for (int s = SB / 2; s > 0; s >>= 1) {
        if (threadIdx.x < s) red[threadIdx.x] += red[threadIdx.x + s];
        __syncthreads();
    }
    if (threadIdx.x == 0) g_bsum[blockIdx.x] = red[0];
}

// 3b) scan pass B: exclusive scan of the 98 block sums (one tiny block).
__global__ __launch_bounds__(128) void scanB_kernel() {
    __shared__ int part[128];
    int t = threadIdx.x;
    int v = (t < NB) ? g_bsum[t] : 0;
    part[t] = v;
    __syncthreads();
    for (int off = 1; off < 128; off <<= 1) {
        int a = part[t];
        int add = (t >= off) ? part[t - off] : 0;
        __syncthreads();
        part[t] = a + add;
        __syncthreads();
    }
    if (t < NB) g_bbase[t] = part[t] - v;           // exclusive
    if (t == 127) g_off[N_NODES] = part[127];       // total = E
}

// 3c) scan pass C: per-block exclusive scan of counts + block base -> g_off/g_cur.
__global__ __launch_bounds__(SB) void scanC_kernel() {
    __shared__ int part[SB];
    int i = blockIdx.x * SB + threadIdx.x;
    int c = (i < N_NODES) ? g_cnt[i] : 0;
    part[threadIdx.x] = c;
    __syncthreads();
    for (int off = 1; off < SB; off <<= 1) {
        int a = part[threadIdx.x];
        int add = (threadIdx.x >= off) ? part[threadIdx.x - off] : 0;
        __syncthreads();
        part[threadIdx.x] = a + add;
        __syncthreads();
    }
    if (i < N_NODES) {
        int excl = part[threadIdx.x] - c + g_bbase[blockIdx.x];
        g_off[i] = excl;
        g_cur[i] = excl;
    }
}

// ---------------------------------------------------------------------------
// 4) reorder edges into CSR-by-target, folding in the normalization weight
__global__ void reorder_kernel(const int* __restrict__ ei,
                               const float* __restrict__ ew) {
    int e = blockIdx.x * blockDim.x + threadIdx.x;
    if (e >= N_EDGES) return;
    int is64 = g_is64;
    int s = edge_src(ei, e, is64);
    int t = edge_dst(ei, e, is64);
    float w = g_dinv[s] * ew[e] * g_dinv[t];
    int pos = atomicAdd(&g_cur[t], 1);
    g_edges[pos] = make_float2(__int_as_float(s), w);
}

// ---------------------------------------------------------------------------
// 5) GEMM: xw[N,64] = x[N,128] @ W[128,64]; fp32 math, fp16 output store.
#define GEMM_ROWS 64
#define XS_STRIDE 132
__global__ __launch_bounds__(256) void gemm_kernel(const float* __restrict__ x,
                                                   const float* __restrict__ W) {
    __shared__ float Ws[IN_CH * OUT_CH];        // 32KB
    __shared__ float Xs[GEMM_ROWS * XS_STRIDE]; // ~33KB
    int node0 = blockIdx.x * GEMM_ROWS;

    for (int i = threadIdx.x; i < IN_CH * OUT_CH / 4; i += 256)
        ((float4*)Ws)[i] = ((const float4*)W)[i];

    for (int i = threadIdx.x; i < GEMM_ROWS * (IN_CH / 4); i += 256) {
        int r = i / (IN_CH / 4);
        int c = i % (IN_CH / 4);
        int node = node0 + r;
        float4 v = make_float4(0.f, 0.f, 0.f, 0.f);
        if (node < N_NODES)
            v = ((const float4*)(x + (size_t)node * IN_CH))[c];
        float* dst = &Xs[r * XS_STRIDE + c * 4];
        dst[0] = v.x; dst[1] = v.y; dst[2] = v.z; dst[3] = v.w;
    }
    __syncthreads();

    int r    = threadIdx.x >> 2;
    int cg   = threadIdx.x & 3;
    int node = node0 + r;

    float acc[16];
#pragma unroll
    for (int j = 0; j < 16; j++) acc[j] = 0.0f;

#pragma unroll 4
    for (int k = 0; k < IN_CH; k++) {
        float xv = Xs[r * XS_STRIDE + k];
#pragma unroll
        for (int j = 0; j < 16; j++)
            acc[j] += xv * Ws[k * OUT_CH + cg + 4 * j];
    }

    if (node < N_NODES) {
        __half* o = g_xw + (size_t)node * OUT_CH;
#pragma unroll
        for (int j = 0; j < 16; j++)
            o[cg + 4 * j] = __float2half(acc[j]);
    }
}

// ---------------------------------------------------------------------------
// 6) gather: out[n] = (2*dinv[n]^2)*xw[n] + b + sum_{e->n} w_e * xw[src_e]
//    16 lanes per node; each lane covers 4 channels (8B fp16 per row read;
//    a full source row is one 128B cache line). fp32 accumulation, no atomics.
__global__ __launch_bounds__(256) void gather_kernel(const float* __restrict__ b,
                                                     float* __restrict__ out) {
    int node = blockIdx.x * 16 + (threadIdx.x >> 4);
    int lane = threadIdx.x & 15;
    if (node >= N_NODES) return;

    union Cvt { uint2 u; __half2 h[2]; };

    float d  = g_dinv[node];
    float sw = SELF_LOOP_W * d * d;

    Cvt self;
    self.u = *(const uint2*)(g_xw + (size_t)node * OUT_CH + lane * 4);
    float2 s0 = __half22float2(self.h[0]);
    float2 s1 = __half22float2(self.h[1]);
    float4 bb = ((const float4*)b)[lane];
    float4 acc = make_float4(fmaf(s0.x, sw, bb.x), fmaf(s0.y, sw, bb.y),
                             fmaf(s1.x, sw, bb.z), fmaf(s1.y, sw, bb.w));

    int beg = g_off[node];
    int end = g_off[node + 1];
#pragma unroll 4
    for (int j = beg; j < end; j++) {
        float2 m = g_edges[j];
        int   s = __float_as_int(m.x);
        float w = m.y;
        Cvt cv;
        cv.u = *(const uint2*)(g_xw + (size_t)s * OUT_CH + lane * 4);
        float2 u0 = __half22float2(cv.h[0]);
        float2 u1 = __half22float2(cv.h[1]);
        acc.x = fmaf(u0.x, w, acc.x);
        acc.y = fmaf(u0.y, w, acc.y);
        acc.z = fmaf(u1.x, w, acc.z);
        acc.w = fmaf(u1.y, w, acc.w);
    }
    ((float4*)out)[node * 16 + lane] = acc;
}

// ---------------------------------------------------------------------------
extern "C" void kernel_launch(void* const* d_in, const int* in_sizes, int n_in,
                              void* d_out, int out_size) {
    const float* x  = (const float*)d_in[0];   // [N, 128]
    const int*   ei = (const int*)d_in[1];     // [2, E] int32 or int64 (detected)
    const float* ew = (const float*)d_in[2];   // [E]
    const float* W  = (const float*)d_in[3];   // [128, 64]
    const float* b  = (const float*)d_in[4];   // [64]
    float* out = (float*)d_out;                // [N, 64]
    (void)in_sizes; (void)n_in; (void)out_size;

    prep_kernel<<<(N_NODES + 255) / 256, 256>>>((const unsigned*)d_in[1]);
    hist_kernel<<<(N_EDGES + 255) / 256, 256>>>(ei, ew);
    scanA_kernel<<<NB, SB>>>();
    scanB_kernel<<<1, 128>>>();
    scanC_kernel<<<NB, SB>>>();
    reorder_kernel<<<(N_EDGES + 255) / 256, 256>>>(ei, ew);
    gemm_kernel<<<(N_NODES + GEMM_ROWS - 1) / GEMM_ROWS, 256>>>(x, W);
    gather_kernel<<<(N_NODES + 15) / 16, 256>>>(b, out);
}

// round 17
// speedup vs baseline: 2.2643x; 1.0184x over previous
#include <cuda_runtime.h>
#include <cuda_fp16.h>
#include <cstdint>

// Problem constants (fixed by the reference)
#define N_NODES 50000
#define N_EDGES 800000
#define IN_CH   128
#define OUT_CH  64
#define SELF_LOOP_W 2.0f

#define SB 512                               // scan block size
#define NB ((N_NODES + SB - 1) / SB)         // 98 scan blocks

#define GR 32                                // gemm rows per block
#define GEMM_NB ((N_NODES + GR - 1) / GR)    // 1563
#define EDGE_NB ((N_EDGES + 255) / 256)      // 3125
#define XS_STRIDE 132

// Scratch (device globals: no allocation allowed).
// g_cd is zero at module load and re-zeroed by scan_kernel every call.
// g_total grows by exactly N_EDGES per call -> (value % N_EDGES)==0 at call start.
__device__ unsigned long long g_cd[N_NODES]; // packed: count<<32 | fix24(sum ew)
__device__ unsigned long long g_total;
__device__ float  g_dinv[N_NODES];
__device__ int    g_cnt[N_NODES];
__device__ int    g_off[N_NODES];
__device__ int    g_cur[N_NODES];
__device__ float2 g_edges[N_EDGES];          // (src bits, normalized weight), CSR by target
__device__ __half g_xw[N_NODES * OUT_CH];    // fp16 transformed features (6.4MB)

// ---------------------------------------------------------------------------
// Per-block dtype sniff: sample 8 odd 32-bit words (max index 1,260,001 <
// 1,600,000 words = the smaller int32 layout). int64 input => all are zero
// high halves. int32 input => random node ids, all-zero prob (2e-5)^8 ~ 0.
__device__ __forceinline__ int block_sniff(const unsigned* __restrict__ p32,
                                           int* flag_sh) {
    if (threadIdx.x == 0) {
        unsigned acc = 0;
#pragma unroll
        for (int k = 0; k < 8; k++) acc |= p32[2 * k * 90000 + 1];
        *flag_sh = (acc == 0) ? 1 : 0;
    }
    __syncthreads();
    return *flag_sh;
}

__device__ __forceinline__ int edge_src(const int* __restrict__ p32, int e, int is64) {
    int v = is64 ? p32[2 * e] : p32[e];
    return (unsigned)v < N_NODES ? v : 0;
}
__device__ __forceinline__ int edge_dst(const int* __restrict__ p32, int e, int is64) {
    int v = is64 ? p32[2 * (N_EDGES + e)] : p32[N_EDGES + e];
    return (unsigned)v < N_NODES ? v : 0;
}

// ---------------------------------------------------------------------------
// 1) histogram + degree in ONE 64-bit atomic per edge:
//    high 32: edge count; low 32: sum of ew in 8.24 fixed point.
__global__ __launch_bounds__(256) void hist_kernel(const int* __restrict__ ei,
                                                   const float* __restrict__ ew) {
    __shared__ int flag;
    int is64 = block_sniff((const unsigned*)ei, &flag);
    int e = blockIdx.x * 256 + threadIdx.x;
    if (e >= N_EDGES) return;
    int t = edge_dst(ei, e, is64);
    unsigned fx = __float2uint_rn(ew[e] * 16777216.0f);   // ew in [0,1)
    atomicAdd(&g_cd[t], (1ULL << 32) | (unsigned long long)fx);
}

// ---------------------------------------------------------------------------
// 2) merged scan: unpack count + dinv, zero g_cd, block-local inclusive scan,
//    block base via monotone u64 atomic counter (base % E = per-call offset).
__global__ __launch_bounds__(SB) void scan_kernel() {
    __shared__ int part[SB];
    __shared__ unsigned base_sh;
    int i = blockIdx.x * SB + threadIdx.x;
    int c = 0;
    if (i < N_NODES) {
        unsigned long long cd = g_cd[i];
        g_cd[i] = 0ULL;                      // re-arm for the next call
        c = (int)(cd >> 32);
        float deg = SELF_LOOP_W + (float)(unsigned)cd * (1.0f / 16777216.0f);
        g_dinv[i] = rsqrtf(deg);             // deg >= 2 always
        g_cnt[i]  = c;
    }
    part[threadIdx.x] = c;
    __syncthreads();
    for (int off = 1; off < SB; off <<= 1) {
        int a = part[threadIdx.x];
        int add = (threadIdx.x >= off) ? part[threadIdx.x - off] : 0;
        __syncthreads();
        part[threadIdx.x] = a + add;
        __syncthreads();
    }
    if (threadIdx.x == 0) {
        unsigned long long tot = (unsigned long long)part[SB - 1];
        unsigned long long base = atomicAdd(&g_total, tot);
        base_sh = (unsigned)(base % (unsigned long long)N_EDGES);
    }
    __syncthreads();
    if (i < N_NODES) {
        int excl = part[threadIdx.x] - c + (int)base_sh;
        g_off[i] = excl;
        g_cur[i] = excl;
    }
}

// ---------------------------------------------------------------------------
// 3) fused gemm + reorder (independent work, partitioned by blockIdx).
//    gemm blocks [0, GEMM_NB):  xw[32 rows] = x @ W, fp32 math, fp16 store.
//    edge blocks [GEMM_NB, +EDGE_NB): CSR reorder with folded norm weight.
__global__ __launch_bounds__(256) void gemm_reorder_kernel(
    const float* __restrict__ x, const float* __restrict__ W,
    const int* __restrict__ ei, const float* __restrict__ ew) {
    __shared__ float sh[IN_CH * OUT_CH + GR * XS_STRIDE];   // 49.7KB

    if (blockIdx.x < GEMM_NB) {
        float* Ws = sh;
        float* Xs = sh + IN_CH * OUT_CH;
        int node0 = blockIdx.x * GR;

        for (int i = threadIdx.x; i < IN_CH * OUT_CH / 4; i += 256)
            ((float4*)Ws)[i] = ((const float4*)W)[i];

        for (int i = threadIdx.x; i < GR * (IN_CH / 4); i += 256) {
            int r = i / (IN_CH / 4);
            int c = i % (IN_CH / 4);
            int node = node0 + r;
            float4 v = make_float4(0.f, 0.f, 0.f, 0.f);
            if (node < N_NODES)
                v = ((const float4*)(x + (size_t)node * IN_CH))[c];
            float* dst = &Xs[r * XS_STRIDE + c * 4];
            dst[0] = v.x; dst[1] = v.y; dst[2] = v.z; dst[3] = v.w;
        }
        __syncthreads();

        int r  = threadIdx.x >> 3;          // 0..31
        int cg = threadIdx.x & 7;           // cols cg + 8*j
        int node = node0 + r;

        float acc[8];
#pragma unroll
        for (int j = 0; j < 8; j++) acc[j] = 0.0f;

#pragma unroll 4
        for (int k = 0; k < IN_CH; k++) {
            float xv = Xs[r * XS_STRIDE + k];
#pragma unroll
            for (int j = 0; j < 8; j++)
                acc[j] += xv * Ws[k * OUT_CH + cg + 8 * j];
        }

        if (node < N_NODES) {
            __half* o = g_xw + (size_t)node * OUT_CH;
#pragma unroll
            for (int j = 0; j < 8; j++)
                o[cg + 8 * j] = __float2half(acc[j]);
        }
    } else {
        int is64 = block_sniff((const unsigned*)ei, (int*)sh);
        int e = (blockIdx.x - GEMM_NB) * 256 + threadIdx.x;
        if (e < N_EDGES) {
            int s = edge_src(ei, e, is64);
            int t = edge_dst(ei, e, is64);
            float w = g_dinv[s] * ew[e] * g_dinv[t];
            int pos = atomicAdd(&g_cur[t], 1);
            g_edges[pos] = make_float2(__int_as_float(s), w);
        }
    }
}

// ---------------------------------------------------------------------------
// 4) gather: out[n] = (2*dinv[n]^2)*xw[n] + b + sum_{e->n} w_e * xw[src_e]
//    16 lanes per node, 8B fp16 per lane (full source row = one 128B line),
//    fp32 accumulation, no atomics. End bound = beg + cnt (bases may be
//    block-permuted, so g_off[n+1] is NOT the end).
__global__ __launch_bounds__(256) void gather_kernel(const float* __restrict__ b,
                                                     float* __restrict__ out) {
    int node = blockIdx.x * 16 + (threadIdx.x >> 4);
    int lane = threadIdx.x & 15;
    if (node >= N_NODES) return;

    union Cvt { uint2 u; __half2 h[2]; };

    float d  = g_dinv[node];
    float sw = SELF_LOOP_W * d * d;

    Cvt self;
    self.u = *(const uint2*)(g_xw + (size_t)node * OUT_CH + lane * 4);
    float2 s0 = __half22float2(self.h[0]);
    float2 s1 = __half22float2(self.h[1]);
    float4 bb = ((const float4*)b)[lane];
    float4 acc = make_float4(fmaf(s0.x, sw, bb.x), fmaf(s0.y, sw, bb.y),
                             fmaf(s1.x, sw, bb.z), fmaf(s1.y, sw, bb.w));

    int beg = g_off[node];
    int end = beg + g_cnt[node];
#pragma unroll 4
    for (int j = beg; j < end; j++) {
        float2 m = g_edges[j];
        int   s = __float_as_int(m.x);
        float w = m.y;
        Cvt cv;
        cv.u = *(const uint2*)(g_xw + (size_t)s * OUT_CH + lane * 4);
        float2 u0 = __half22float2(cv.h[0]);
        float2 u1 = __half22float2(cv.h[1]);
        acc.x = fmaf(u0.x, w, acc.x);
        acc.y = fmaf(u0.y, w, acc.y);
        acc.z = fmaf(u1.x, w, acc.z);
        acc.w = fmaf(u1.y, w, acc.w);
    }
    ((float4*)out)[node * 16 + lane] = acc;
}

// ---------------------------------------------------------------------------
extern "C" void kernel_launch(void* const* d_in, const int* in_sizes, int n_in,
                              void* d_out, int out_size) {
    const float* x  = (const float*)d_in[0];   // [N, 128]
    const int*   ei = (const int*)d_in[1];     // [2, E] int32 or int64 (sniffed)
    const float* ew = (const float*)d_in[2];   // [E]
    const float* W  = (const float*)d_in[3];   // [128, 64]
    const float* b  = (const float*)d_in[4];   // [64]
    float* out = (float*)d_out;                // [N, 64]
    (void)in_sizes; (void)n_in; (void)out_size;

    hist_kernel<<<EDGE_NB, 256>>>(ei, ew);
    scan_kernel<<<NB, SB>>>();
    gemm_reorder_kernel<<<GEMM_NB + EDGE_NB, 256>>>(x, W, ei, ew);
    gather_kernel<<<(N_NODES + 15) / 16, 256>>>(b, out);
}